// round 9
// baseline (speedup 1.0000x reference)
#include <cuda_runtime.h>
#include <cstdint>
#include <cstddef>

#define BATCH 1024
#define LSEQ  512
#define DIM   64
#define KCAP  8
#define NEGV  (-65535.0f)
#define NTHREADS 1024
#define GRID  148
#define CPS 10

// ---- shared memory layout (float offsets) ----
#define WT0_OFF   0          // W^T buf0 [512][8]          4096
#define WT1_OFF   4096       // W^T buf1 [512][8]          4096
#define XS_OFF    8192       // X [512][64] 16B-chunk swizzled     32768
#define SS_OFF    40960      // S [64][67]                 4288
#define CPART_OFF 45248      // pass1 partials [16][64][10] 10240
#define CPT_OFF   55488      // C'^T [64][8]               512
#define HO_OFF    56000      // Cs/high transposed [64][10] 640
#define SCALE_OFF 56640      // squash scale [64]          64
#define HST_OFF   56704      // hs^T [64][8]               512
#define SMEM_FLOATS 57216
#define SMEM_BYTES  (SMEM_FLOATS * 4)   // 228864 B (<= 232448 opt-in)

__device__ float g_B[KCAP * LSEQ];
__device__ float g_scratch[BATCH * KCAP * LSEQ];   // per-batch deltas, layout [b][l][k]
__device__ float g_part[64 * KCAP * LSEQ];         // stage-1 partials, layout [y][l][k]

__device__ __forceinline__ void cp_async16(uint32_t sa, const void* ga) {
    asm volatile("cp.async.cg.shared.global [%0], [%1], 16;" :: "r"(sa), "l"(ga));
}
__device__ __forceinline__ void cp_commit() {
    asm volatile("cp.async.commit_group;" ::: "memory");
}
template<int N>
__device__ __forceinline__ void cp_wait() {
    asm volatile("cp.async.wait_group %0;" :: "n"(N) : "memory");
}
__device__ __forceinline__ void bar_epi() {   // named barrier: warps 8..15 (256 thr)
    asm volatile("bar.sync 1, 256;" ::: "memory");
}
__device__ __forceinline__ unsigned long long pack2(float v) {
    unsigned long long r;
    asm("mov.b64 %0, {%1, %1};" : "=l"(r) : "r"(__float_as_uint(v)));
    return r;
}
__device__ __forceinline__ void fma2(unsigned long long& acc,
                                     unsigned long long a, unsigned long long b) {
    asm("fma.rn.f32x2 %0, %1, %2, %0;" : "+l"(acc) : "l"(a), "l"(b));
}
__device__ __forceinline__ unsigned long long add2(unsigned long long a,
                                                   unsigned long long b) {
    unsigned long long r;
    asm("add.rn.f32x2 %0, %1, %2;" : "=l"(r) : "l"(a), "l"(b));
    return r;
}
__device__ __forceinline__ unsigned long long mul2(unsigned long long a,
                                                   unsigned long long b) {
    unsigned long long r;
    asm("mul.rn.f32x2 %0, %1, %2;" : "=l"(r) : "l"(a), "l"(b));
    return r;
}

// Issue this warp's 16 X rows (2 commit groups of 8 rows), swizzled store.
__device__ __forceinline__ void issue_rows(const float* __restrict__ X, int b,
                                           uint32_t xs_base, int row0, int lane) {
    const float* Xg = X + (size_t)b * (LSEQ * DIM);
    #pragma unroll
    for (int g2 = 0; g2 < 2; g2++) {
        #pragma unroll
        for (int h = 0; h < 4; h++) {
            int s   = lane + 32 * h;               // 0..127
            int r8  = s >> 4;
            int col = s & 15;                      // 16B data chunk
            int row = row0 + 8 * g2 + r8;
            int sw  = col ^ (row & 15);            // swizzled chunk
            cp_async16(xs_base + (uint32_t)(row * 256 + sw * 16),
                       (const void*)(Xg + row * DIM + col * 4));
        }
        cp_commit();
    }
}

// Masked softmax for batch b into wt (warps 0..7 only; k = warp id).
__device__ __forceinline__ void do_softmax(float* __restrict__ wt,
                                           const int* __restrict__ seqlen,
                                           int b, int k, int lane) {
    const int slen = seqlen[b];
    float v[16];
    #pragma unroll
    for (int j = 0; j < 16; j++) {
        int l = lane + 32 * j;
        float bv = g_B[k * LSEQ + l];
        v[j] = (l < slen) ? bv : NEGV;
    }
    float m = v[0];
    #pragma unroll
    for (int j = 1; j < 16; j++) m = fmaxf(m, v[j]);
    #pragma unroll
    for (int off = 16; off > 0; off >>= 1)
        m = fmaxf(m, __shfl_xor_sync(0xffffffffu, m, off));
    float s = 0.f;
    #pragma unroll
    for (int j = 0; j < 16; j++) { v[j] = __expf(v[j] - m); s += v[j]; }
    #pragma unroll
    for (int off = 16; off > 0; off >>= 1)
        s += __shfl_xor_sync(0xffffffffu, s, off);
    float inv = 1.0f / s;
    #pragma unroll
    for (int j = 0; j < 16; j++)
        wt[(lane + 32 * j) * 8 + k] = v[j] * inv;   // W^T[l][k]
}

// Persistent kernel: one routing iteration. Warp-specialized step 4:
// warps 0-7 softmax(n+1), warps 8-15 packed epilogue, warps 16-31 idle.
template<int LAST>
__global__ void __launch_bounds__(NTHREADS, 1)
route_kernel(const float* __restrict__ X, const float* __restrict__ Sg,
             const int* __restrict__ seqlen, float* __restrict__ out)
{
    extern __shared__ float sm[];
    const int tid  = threadIdx.x;
    const int w    = tid >> 5;            // 32 warps
    const int lane = tid & 31;
    const uint32_t xs_base = (uint32_t)__cvta_generic_to_shared(&sm[XS_OFF]);
    const int row0 = w * 16;              // this warp's X rows [row0, row0+16)

    int b = blockIdx.x;

    // prologue
    issue_rows(X, b, xs_base, row0, lane);
    {
        int j = tid;                      // 1024 float4s = S [64][64]
        int d = j >> 4, o4 = (j & 15) * 4;
        float4 v = *(const float4*)(Sg + j * 4);
        float* p = &sm[SS_OFF + d * 67 + o4];
        p[0] = v.x; p[1] = v.y; p[2] = v.z; p[3] = v.w;
    }
    if (w < 8) do_softmax(&sm[WT0_OFF], seqlen, b, w, lane);
    __syncthreads();

    int par = 0;
    for (; b < BATCH; b += GRID, par ^= 1) {
        const int bn = b + GRID;
        const float* wt  = &sm[par ? WT1_OFF : WT0_OFF];
        float*       wtn = &sm[par ? WT0_OFF : WT1_OFF];

        // ---- pass 1: C'[k][d] = sum_l W[k][l]*X[l][d]; warp-private rows ----
        unsigned long long acc2[8];
        #pragma unroll
        for (int i = 0; i < 8; i++) acc2[i] = 0ull;

        #pragma unroll
        for (int g2 = 0; g2 < 2; g2++) {
            if (g2 == 0) cp_wait<1>(); else cp_wait<0>();
            __syncwarp();
            #pragma unroll
            for (int r = 0; r < 8; r++) {
                int row = row0 + 8 * g2 + r;
                int rsw = row & 15;
                float2 xv = *(const float2*)&sm[XS_OFF + row * 64 +
                                                (((lane >> 1) ^ rsw) << 2) + (lane & 1) * 2];
                ulonglong2 wA = *(const ulonglong2*)&wt[row * 8];
                ulonglong2 wB = *(const ulonglong2*)&wt[row * 8 + 4];
                unsigned long long xx0 = pack2(xv.x);
                unsigned long long xx1 = pack2(xv.y);
                fma2(acc2[0], xx0, wA.x); fma2(acc2[1], xx0, wA.y);
                fma2(acc2[2], xx0, wB.x); fma2(acc2[3], xx0, wB.y);
                fma2(acc2[4], xx1, wA.x); fma2(acc2[5], xx1, wA.y);
                fma2(acc2[6], xx1, wB.x); fma2(acc2[7], xx1, wB.y);
            }
        }

        // LAST: X dead after pass1 -> prefetch own rows now
        if (LAST && bn < BATCH) issue_rows(X, bn, xs_base, row0, lane);

        // ---- two-wave cross-warp reduction into CPART [16][64][10] ----
        if (w < 16) {
            #pragma unroll
            for (int dd = 0; dd < 2; dd++)
                #pragma unroll
                for (int kp = 0; kp < 4; kp++) {
                    int d = 2 * lane + dd;
                    *(unsigned long long*)&sm[CPART_OFF + w * 640 + d * CPS + 2 * kp]
                        = acc2[dd * 4 + kp];
                }
        }
        __syncthreads();
        if (w >= 16) {
            int p = w - 16;
            #pragma unroll
            for (int dd = 0; dd < 2; dd++)
                #pragma unroll
                for (int kp = 0; kp < 4; kp++) {
                    int d = 2 * lane + dd;
                    unsigned long long* ptr =
                        (unsigned long long*)&sm[CPART_OFF + p * 640 + d * CPS + 2 * kp];
                    *ptr = add2(*ptr, acc2[dd * 4 + kp]);
                }
        }
        __syncthreads();
        if (tid < 512) {                       // C'^T[d][k]
            int k = tid & 7, d = tid >> 3;
            float s = 0.f;
            #pragma unroll
            for (int p = 0; p < 16; p++) s += sm[CPART_OFF + p * 640 + d * CPS + k];
            sm[CPT_OFF + d * 8 + k] = s;
        }
        __syncthreads();

        // ---- step 4: softmax(n+1) on warps 0-7 || packed epilogue on warps 8-15 ----
        if (w < 8) {
            if (bn < BATCH) do_softmax(wtn, seqlen, bn, w, lane);
        } else if (w < 16) {
            const int t  = tid - 256;         // 0..255
            const int kp = t >> 6;            // capsule pair (2kp, 2kp+1)
            const int o  = t & 63;

            // Cs pair: acc = sum_d CPT[d][kpair] * splat(S[d][o])
            unsigned long long a = 0ull;
            #pragma unroll
            for (int d = 0; d < 64; d++) {
                unsigned long long cp2 = *(const unsigned long long*)&sm[CPT_OFF + d * 8 + 2 * kp];
                fma2(a, pack2(sm[SS_OFF + d * 67 + o]), cp2);
            }
            *(unsigned long long*)&sm[HO_OFF + o * 10 + 2 * kp] = a;
            bar_epi();

            if (t < 64) {                     // squash scale
                float sq = 0.f;
                #pragma unroll
                for (int k8 = 0; k8 < 8; k8++) {
                    float cv = sm[HO_OFF + t * 10 + k8];
                    sq += cv * cv;
                }
                sm[SCALE_OFF + t] = (sq / (1.0f + sq)) * rsqrtf(sq + 1e-9f);
            }
            bar_epi();

            // scale -> high (packed)
            unsigned long long hv = mul2(*(unsigned long long*)&sm[HO_OFF + o * 10 + 2 * kp],
                                         pack2(sm[SCALE_OFF + o]));
            if (LAST) {
                unsigned int u0, u1;
                asm("mov.b64 {%0, %1}, %2;" : "=r"(u0), "=r"(u1) : "l"(hv));
                out[(size_t)b * 512 + (2 * kp) * 64 + o]     = __uint_as_float(u0);
                out[(size_t)b * 512 + (2 * kp + 1) * 64 + o] = __uint_as_float(u1);
            } else {
                *(unsigned long long*)&sm[HO_OFF + o * 10 + 2 * kp] = hv;
                bar_epi();
                // hs pair: acc = sum_o2 HO[o2][kpair] * splat(S[i][o2]);  i := o
                const int i = o;
                unsigned long long h = 0ull;
                #pragma unroll
                for (int o2 = 0; o2 < 64; o2++) {
                    unsigned long long ho2 =
                        *(const unsigned long long*)&sm[HO_OFF + o2 * 10 + 2 * kp];
                    fma2(h, pack2(sm[SS_OFF + i * 67 + o2]), ho2);
                }
                *(unsigned long long*)&sm[HST_OFF + i * 8 + 2 * kp] = h;
            }
        }
        __syncthreads();   // publishes wtn + HST

        if (!LAST) {
            // ---- pass 2 (own rows, i-split): delta[k][l] = sum_i hs[k][i]*X[l][i] ----
            const int row = row0 + (lane >> 1);
            const int ks  = lane & 1;          // i-half owner; final caps [4ks,4ks+4)
            const int rsw = row & 15;
            unsigned long long dall[4] = {0ull, 0ull, 0ull, 0ull};  // all 8 caps
            #pragma unroll
            for (int q = 0; q < 8; q++) {
                int c = ks * 8 + q;            // 16B chunk = i [4c, 4c+4)
                float4 x = *(const float4*)&sm[XS_OFF + row * 64 + ((c ^ rsw) << 2)];
                #pragma unroll
                for (int r = 0; r < 4; r++) {
                    float xvf = (r == 0) ? x.x : (r == 1) ? x.y : (r == 2) ? x.z : x.w;
                    unsigned long long xx = pack2(xvf);
                    ulonglong2 hA = *(const ulonglong2*)&sm[HST_OFF + (c * 4 + r) * 8];
                    ulonglong2 hB = *(const ulonglong2*)&sm[HST_OFF + (c * 4 + r) * 8 + 4];
                    fma2(dall[0], xx, hA.x); fma2(dall[1], xx, hA.y);
                    fma2(dall[2], xx, hB.x); fma2(dall[3], xx, hB.y);
                }
            }
            // exchange i-half partials for own capsule group across the lane pair
            const int po = 2 - 2 * ks;         // peer's capsule-pair slots
            unsigned long long r0 = __shfl_xor_sync(0xffffffffu, dall[po], 1);
            unsigned long long r1 = __shfl_xor_sync(0xffffffffu, dall[po + 1], 1);
            unsigned long long m0 = add2(dall[2 * ks],     r0);
            unsigned long long m1 = add2(dall[2 * ks + 1], r1);

            // own rows dead -> prefetch next batch (no barrier to next pass1)
            if (bn < BATCH) issue_rows(X, bn, xs_base, row0, lane);

            // scratch layout [b][l][k]: one coalesced STG.128 per thread
            ulonglong2 st; st.x = m0; st.y = m1;
            *(ulonglong2*)&g_scratch[(size_t)b * 4096 + row * 8 + 4 * ks] = st;
        }
    }
}

// Deterministic 2-stage cross-batch reduction of deltas into g_B ([l][k] layout)
__global__ void reduce1_kernel() {
    int j = blockIdx.x * 256 + threadIdx.x;      // 0..4095 over [l][k]
    int base = blockIdx.y * 16;
    float s = 0.f;
    #pragma unroll
    for (int i = 0; i < 16; i++) s += g_scratch[(size_t)(base + i) * 4096 + j];
    g_part[(size_t)blockIdx.y * 4096 + j] = s;
}
__global__ void reduce2_kernel() {
    int j = blockIdx.x * 256 + threadIdx.x;      // [l][k] index
    float s = 0.f;
    #pragma unroll
    for (int i = 0; i < 64; i++) s += g_part[(size_t)i * 4096 + j];
    int l = j >> 3, k = j & 7;
    g_B[k * 512 + l] += s;
}

extern "C" void kernel_launch(void* const* d_in, const int* in_sizes, int n_in,
                              void* d_out, int out_size)
{
    const float* X     = (const float*)d_in[0];  // low_capsule [1024,512,64]
    const float* Binit = (const float*)d_in[1];  // B_init [1,8,512]
    const float* S     = (const float*)d_in[2];  // S [64,64]
    const int*   seq   = (const int*)d_in[3];    // seq_len [1024,1]
    float* out = (float*)d_out;

    cudaFuncSetAttribute(route_kernel<0>, cudaFuncAttributeMaxDynamicSharedMemorySize, SMEM_BYTES);
    cudaFuncSetAttribute(route_kernel<1>, cudaFuncAttributeMaxDynamicSharedMemorySize, SMEM_BYTES);

    void* bptr = nullptr;
    cudaGetSymbolAddress(&bptr, g_B);
    cudaMemcpyAsync(bptr, Binit, KCAP * LSEQ * sizeof(float),
                    cudaMemcpyDeviceToDevice, 0);

    // iter 0
    route_kernel<0><<<GRID, NTHREADS, SMEM_BYTES>>>(X, S, seq, out);
    reduce1_kernel<<<dim3(16, 64), 256>>>();
    reduce2_kernel<<<16, 256>>>();
    // iter 1
    route_kernel<0><<<GRID, NTHREADS, SMEM_BYTES>>>(X, S, seq, out);
    reduce1_kernel<<<dim3(16, 64), 256>>>();
    reduce2_kernel<<<16, 256>>>();
    // iter 2 (final): writes high
    route_kernel<1><<<GRID, NTHREADS, SMEM_BYTES>>>(X, S, seq, out);
}

// round 10
// speedup vs baseline: 1.0057x; 1.0057x over previous
#include <cuda_runtime.h>
#include <cstdint>
#include <cstddef>

#define BATCH 1024
#define LSEQ  512
#define DIM   64
#define KCAP  8
#define NEGV  (-65535.0f)
#define NTHREADS 1024
#define GRID  148
#define CPS 10

// ---- shared memory layout (float offsets) ----
#define WT0_OFF   0          // W^T buf0 [512][8]      4096
#define WT1_OFF   4096       // W^T buf1 [512][8]      4096
#define XS_OFF    8192       // X [512][64], 16B-chunk swizzled (chunk ^= row&15)
#define SS_OFF    40960      // S [64][67]             4288
#define CPART_OFF 45248      // pass1 partials [16][64][10]  10240
#define CP_OFF    55488      // C' [8][64]             512
#define CS_OFF    56000      // Cs/high [8][65]        520
#define SCALE_OFF 56520      // squash scale [64]      64
#define HST_OFF   56584      // hs^T [64][8]           512
#define SMEM_FLOATS 57096
#define SMEM_BYTES  (SMEM_FLOATS * 4)   // 228384 B (<= 232448 opt-in)

__device__ float g_B[KCAP * LSEQ];
__device__ float g_scratch[BATCH * KCAP * LSEQ];   // per-batch deltas, layout [b][l][k]
__device__ float g_part[64 * KCAP * LSEQ];         // stage-1 partials, layout [y][l][k]

__device__ __forceinline__ void cp_async16(uint32_t sa, const void* ga) {
    asm volatile("cp.async.cg.shared.global [%0], [%1], 16;" :: "r"(sa), "l"(ga));
}
__device__ __forceinline__ void cp_commit() {
    asm volatile("cp.async.commit_group;" ::: "memory");
}
template<int N>
__device__ __forceinline__ void cp_wait() {
    asm volatile("cp.async.wait_group %0;" :: "n"(N) : "memory");
}
__device__ __forceinline__ void bar_epi() {   // named barrier: warps 8..23 (512 thr)
    asm volatile("bar.sync 1, 512;" ::: "memory");
}
__device__ __forceinline__ unsigned long long pack2(float v) {
    unsigned long long r;
    asm("mov.b64 %0, {%1, %1};" : "=l"(r) : "r"(__float_as_uint(v)));
    return r;
}
__device__ __forceinline__ void fma2(unsigned long long& acc,
                                     unsigned long long a, unsigned long long b) {
    asm("fma.rn.f32x2 %0, %1, %2, %0;" : "+l"(acc) : "l"(a), "l"(b));
}
__device__ __forceinline__ unsigned long long add2(unsigned long long a,
                                                   unsigned long long b) {
    unsigned long long r;
    asm("add.rn.f32x2 %0, %1, %2;" : "=l"(r) : "l"(a), "l"(b));
    return r;
}

// Issue this warp's 16 X rows (2 commit groups of 8 rows), swizzled store.
__device__ __forceinline__ void issue_rows(const float* __restrict__ X, int b,
                                           uint32_t xs_base, int row0, int lane) {
    const float* Xg = X + (size_t)b * (LSEQ * DIM);
    #pragma unroll
    for (int g2 = 0; g2 < 2; g2++) {
        #pragma unroll
        for (int h = 0; h < 4; h++) {
            int s   = lane + 32 * h;               // 0..127
            int r8  = s >> 4;
            int col = s & 15;                      // 16B data chunk
            int row = row0 + 8 * g2 + r8;
            int sw  = col ^ (row & 15);            // swizzled chunk
            cp_async16(xs_base + (uint32_t)(row * 256 + sw * 16),
                       (const void*)(Xg + row * DIM + col * 4));
        }
        cp_commit();
    }
}

// Masked softmax for batch b into wt (warps 0..7 only; k = warp id).
__device__ __forceinline__ void do_softmax(float* __restrict__ wt,
                                           const int* __restrict__ seqlen,
                                           int b, int k, int lane) {
    const int slen = seqlen[b];
    float v[16];
    #pragma unroll
    for (int j = 0; j < 16; j++) {
        int l = lane + 32 * j;
        float bv = g_B[k * LSEQ + l];
        v[j] = (l < slen) ? bv : NEGV;
    }
    float m = v[0];
    #pragma unroll
    for (int j = 1; j < 16; j++) m = fmaxf(m, v[j]);
    #pragma unroll
    for (int off = 16; off > 0; off >>= 1)
        m = fmaxf(m, __shfl_xor_sync(0xffffffffu, m, off));
    float s = 0.f;
    #pragma unroll
    for (int j = 0; j < 16; j++) { v[j] = __expf(v[j] - m); s += v[j]; }
    #pragma unroll
    for (int off = 16; off > 0; off >>= 1)
        s += __shfl_xor_sync(0xffffffffu, s, off);
    float inv = 1.0f / s;
    #pragma unroll
    for (int j = 0; j < 16; j++)
        wt[(lane + 32 * j) * 8 + k] = v[j] * inv;   // W^T[l][k]
}

// Persistent kernel: one routing iteration. Warp-specialized step 4:
// warps 0-7 softmax(n+1), warps 8-23 epilogue, warps 24-31 idle.
template<int LAST>
__global__ void __launch_bounds__(NTHREADS, 1)
route_kernel(const float* __restrict__ X, const float* __restrict__ Sg,
             const int* __restrict__ seqlen, float* __restrict__ out)
{
    extern __shared__ float sm[];
    const int tid  = threadIdx.x;
    const int w    = tid >> 5;            // 32 warps
    const int lane = tid & 31;
    const uint32_t xs_base = (uint32_t)__cvta_generic_to_shared(&sm[XS_OFF]);
    const int row0 = w * 16;              // this warp's X rows [row0, row0+16)

    int b = blockIdx.x;

    // prologue
    issue_rows(X, b, xs_base, row0, lane);
    {
        int j = tid;                      // 1024 float4s = S [64][64]
        int d = j >> 4, o4 = (j & 15) * 4;
        float4 v = *(const float4*)(Sg + j * 4);
        float* p = &sm[SS_OFF + d * 67 + o4];
        p[0] = v.x; p[1] = v.y; p[2] = v.z; p[3] = v.w;
    }
    if (w < 8) do_softmax(&sm[WT0_OFF], seqlen, b, w, lane);
    __syncthreads();

    int par = 0;
    for (; b < BATCH; b += GRID, par ^= 1) {
        const int bn = b + GRID;
        const float* wt  = &sm[par ? WT1_OFF : WT0_OFF];
        float*       wtn = &sm[par ? WT0_OFF : WT1_OFF];

        // ---- pass 1: C'[k][d] = sum_l W[k][l]*X[l][d]; warp-private rows ----
        unsigned long long acc2[8];
        #pragma unroll
        for (int i = 0; i < 8; i++) acc2[i] = 0ull;

        #pragma unroll
        for (int g2 = 0; g2 < 2; g2++) {
            if (g2 == 0) cp_wait<1>(); else cp_wait<0>();
            __syncwarp();
            #pragma unroll
            for (int r = 0; r < 8; r++) {
                int row = row0 + 8 * g2 + r;
                int rsw = row & 15;
                float2 xv = *(const float2*)&sm[XS_OFF + row * 64 +
                                                (((lane >> 1) ^ rsw) << 2) + (lane & 1) * 2];
                ulonglong2 wA = *(const ulonglong2*)&wt[row * 8];
                ulonglong2 wB = *(const ulonglong2*)&wt[row * 8 + 4];
                unsigned long long xx0 = pack2(xv.x);
                unsigned long long xx1 = pack2(xv.y);
                fma2(acc2[0], xx0, wA.x); fma2(acc2[1], xx0, wA.y);
                fma2(acc2[2], xx0, wB.x); fma2(acc2[3], xx0, wB.y);
                fma2(acc2[4], xx1, wA.x); fma2(acc2[5], xx1, wA.y);
                fma2(acc2[6], xx1, wB.x); fma2(acc2[7], xx1, wB.y);
            }
        }

        // LAST: X dead after pass1 -> prefetch own rows now
        if (LAST && bn < BATCH) issue_rows(X, bn, xs_base, row0, lane);

        // ---- two-wave cross-warp reduction into CPART [16][64][10] ----
        if (w < 16) {
            #pragma unroll
            for (int dd = 0; dd < 2; dd++)
                #pragma unroll
                for (int kp = 0; kp < 4; kp++) {
                    int d = 2 * lane + dd;
                    *(unsigned long long*)&sm[CPART_OFF + w * 640 + d * CPS + 2 * kp]
                        = acc2[dd * 4 + kp];
                }
        }
        __syncthreads();
        if (w >= 16) {
            int p = w - 16;
            #pragma unroll
            for (int dd = 0; dd < 2; dd++)
                #pragma unroll
                for (int kp = 0; kp < 4; kp++) {
                    int d = 2 * lane + dd;
                    unsigned long long* ptr =
                        (unsigned long long*)&sm[CPART_OFF + p * 640 + d * CPS + 2 * kp];
                    *ptr = add2(*ptr, acc2[dd * 4 + kp]);
                }
        }
        __syncthreads();
        if (tid < 512) {
            int k = tid >> 6, d = tid & 63;
            float s = 0.f;
            #pragma unroll
            for (int p = 0; p < 16; p++) s += sm[CPART_OFF + p * 640 + d * CPS + k];
            sm[CP_OFF + k * 64 + d] = s;
        }
        __syncthreads();

        // ---- step 4: softmax(n+1) on warps 0-7 || epilogue on warps 8-23 ----
        if (w < 8) {
            if (bn < BATCH) do_softmax(wtn, seqlen, bn, w, lane);
        } else if (w < 24) {
            const int t = tid - 256;          // 0..511
            const int k = t >> 6, o = t & 63; // warp spans one k

            // Cs[k][o] = sum_d C'[k][d]*S[d][o]   (2 accumulators)
            float a0 = 0.f, a1 = 0.f;
            #pragma unroll
            for (int d = 0; d < 64; d += 2) {
                a0 += sm[CP_OFF + k * 64 + d]     * sm[SS_OFF + d * 67 + o];
                a1 += sm[CP_OFF + k * 64 + d + 1] * sm[SS_OFF + (d + 1) * 67 + o];
            }
            sm[CS_OFF + k * 65 + o] = a0 + a1;
            bar_epi();

            if (t < 64) {                     // squash scale (2 warps)
                float sq = 0.f;
                #pragma unroll
                for (int k8 = 0; k8 < 8; k8++) {
                    float cv = sm[CS_OFF + k8 * 65 + t];
                    sq += cv * cv;
                }
                sm[SCALE_OFF + t] = (sq / (1.0f + sq)) * rsqrtf(sq + 1e-9f);
            }
            bar_epi();

            float hv = sm[SCALE_OFF + o] * sm[CS_OFF + k * 65 + o];
            if (LAST) {
                out[(size_t)b * 512 + t] = hv;            // t == k*64+o
            } else {
                sm[CS_OFF + k * 65 + o] = hv;             // high, in place
                bar_epi();
                // hs[k][i] = sum_o high[k][o]*S[i][o]  -> hs^T[i][k] (2 accs)
                const int i = o;
                float h0 = 0.f, h1 = 0.f;
                #pragma unroll
                for (int oo = 0; oo < 64; oo += 2) {
                    h0 += sm[CS_OFF + k * 65 + oo]     * sm[SS_OFF + i * 67 + oo];
                    h1 += sm[CS_OFF + k * 65 + oo + 1] * sm[SS_OFF + i * 67 + oo + 1];
                }
                sm[HST_OFF + i * 8 + k] = h0 + h1;
            }
        }
        __syncthreads();   // joins soft/epi/idle; publishes wtn + HST

        if (!LAST) {
            // ---- pass 2 (own rows, i-split): delta[k][l] = sum_i hs[k][i]*X[l][i] ----
            const int row = row0 + (lane >> 1);
            const int ks  = lane & 1;          // i-half owner; final caps [4ks,4ks+4)
            const int rsw = row & 15;
            unsigned long long dall[4] = {0ull, 0ull, 0ull, 0ull};  // all 8 caps
            #pragma unroll
            for (int q = 0; q < 8; q++) {
                int c = ks * 8 + q;            // 16B chunk = i [4c, 4c+4)
                float4 x = *(const float4*)&sm[XS_OFF + row * 64 + ((c ^ rsw) << 2)];
                #pragma unroll
                for (int r = 0; r < 4; r++) {
                    float xvf = (r == 0) ? x.x : (r == 1) ? x.y : (r == 2) ? x.z : x.w;
                    unsigned long long xx = pack2(xvf);
                    ulonglong2 hA = *(const ulonglong2*)&sm[HST_OFF + (c * 4 + r) * 8];
                    ulonglong2 hB = *(const ulonglong2*)&sm[HST_OFF + (c * 4 + r) * 8 + 4];
                    fma2(dall[0], xx, hA.x); fma2(dall[1], xx, hA.y);
                    fma2(dall[2], xx, hB.x); fma2(dall[3], xx, hB.y);
                }
            }
            // exchange i-half partials for own capsule group across the lane pair
            const int po = 2 - 2 * ks;         // peer's capsule-pair slots
            unsigned long long r0 = __shfl_xor_sync(0xffffffffu, dall[po], 1);
            unsigned long long r1 = __shfl_xor_sync(0xffffffffu, dall[po + 1], 1);
            unsigned long long m0 = add2(dall[2 * ks],     r0);
            unsigned long long m1 = add2(dall[2 * ks + 1], r1);

            // own rows dead -> prefetch next batch (no barrier to next pass1)
            if (bn < BATCH) issue_rows(X, bn, xs_base, row0, lane);

            // scratch layout [b][l][k]: one coalesced STG.128 per thread
            ulonglong2 st; st.x = m0; st.y = m1;
            *(ulonglong2*)&g_scratch[(size_t)b * 4096 + row * 8 + 4 * ks] = st;
        }
    }
}

// Deterministic 2-stage cross-batch reduction of deltas into g_B ([l][k] layout)
__global__ void reduce1_kernel() {
    int j = blockIdx.x * 256 + threadIdx.x;      // 0..4095 over [l][k]
    int base = blockIdx.y * 16;
    float s = 0.f;
    #pragma unroll
    for (int i = 0; i < 16; i++) s += g_scratch[(size_t)(base + i) * 4096 + j];
    g_part[(size_t)blockIdx.y * 4096 + j] = s;
}
__global__ void reduce2_kernel() {
    int j = blockIdx.x * 256 + threadIdx.x;      // [l][k] index
    float s = 0.f;
    #pragma unroll
    for (int i = 0; i < 64; i++) s += g_part[(size_t)i * 4096 + j];
    int l = j >> 3, k = j & 7;
    g_B[k * 512 + l] += s;
}

extern "C" void kernel_launch(void* const* d_in, const int* in_sizes, int n_in,
                              void* d_out, int out_size)
{
    const float* X     = (const float*)d_in[0];  // low_capsule [1024,512,64]
    const float* Binit = (const float*)d_in[1];  // B_init [1,8,512]
    const float* S     = (const float*)d_in[2];  // S [64,64]
    const int*   seq   = (const int*)d_in[3];    // seq_len [1024,1]
    float* out = (float*)d_out;

    cudaFuncSetAttribute(route_kernel<0>, cudaFuncAttributeMaxDynamicSharedMemorySize, SMEM_BYTES);
    cudaFuncSetAttribute(route_kernel<1>, cudaFuncAttributeMaxDynamicSharedMemorySize, SMEM_BYTES);

    void* bptr = nullptr;
    cudaGetSymbolAddress(&bptr, g_B);
    cudaMemcpyAsync(bptr, Binit, KCAP * LSEQ * sizeof(float),
                    cudaMemcpyDeviceToDevice, 0);

    // iter 0
    route_kernel<0><<<GRID, NTHREADS, SMEM_BYTES>>>(X, S, seq, out);
    reduce1_kernel<<<dim3(16, 64), 256>>>();
    reduce2_kernel<<<16, 256>>>();
    // iter 1
    route_kernel<0><<<GRID, NTHREADS, SMEM_BYTES>>>(X, S, seq, out);
    reduce1_kernel<<<dim3(16, 64), 256>>>();
    reduce2_kernel<<<16, 256>>>();
    // iter 2 (final): writes high
    route_kernel<1><<<GRID, NTHREADS, SMEM_BYTES>>>(X, S, seq, out);
}

// round 11
// speedup vs baseline: 1.3199x; 1.3124x over previous
#include <cuda_runtime.h>
#include <cstdint>
#include <cstddef>

#define BATCH 1024
#define LSEQ  512
#define DIM   64
#define KCAP  8
#define NEGV  (-65535.0f)
#define NTHREADS 1024
#define GRID  148
#define CPS 10

// ---- shared memory layout (float offsets) ----
#define WT0_OFF   0          // W^T buf0 [512][8]      4096
#define WT1_OFF   4096       // W^T buf1 [512][8]      4096
#define XS_OFF    8192       // X [512][64], 16B-chunk swizzled (chunk ^= row&15)
#define SS_OFF    40960      // S [64][67]             4288
#define CPART_OFF 45248      // pass1 partials [16][64][10]  10240
#define CP_OFF    55488      // C' [8][64]             512
#define CS_OFF    56000      // Cs/high [8][65]        520
#define SCALE_OFF 56520      // squash scale [64]      64
#define HST_OFF   56584      // hs^T [64][8]           512
#define SMEM_FLOATS 57096
#define SMEM_BYTES  (SMEM_FLOATS * 4)   // 228384 B (<= 232448 opt-in)

__device__ float g_B[KCAP * LSEQ];
__device__ float g_scratch[BATCH * KCAP * LSEQ];   // per-batch deltas (16MB), [b][k][l]
__device__ float g_part[64 * KCAP * LSEQ];         // stage-1 reduction partials

__device__ __forceinline__ void cp_async16(uint32_t sa, const void* ga) {
    asm volatile("cp.async.cg.shared.global [%0], [%1], 16;" :: "r"(sa), "l"(ga));
}
__device__ __forceinline__ void cp_commit() {
    asm volatile("cp.async.commit_group;" ::: "memory");
}
template<int N>
__device__ __forceinline__ void cp_wait() {
    asm volatile("cp.async.wait_group %0;" :: "n"(N) : "memory");
}
__device__ __forceinline__ void bar_epi() {   // named barrier: warps 8..23 (512 thr)
    asm volatile("bar.sync 1, 512;" ::: "memory");
}
__device__ __forceinline__ unsigned long long pack2(float v) {
    unsigned long long r;
    asm("mov.b64 %0, {%1, %1};" : "=l"(r) : "r"(__float_as_uint(v)));
    return r;
}
__device__ __forceinline__ void fma2(unsigned long long& acc,
                                     unsigned long long a, unsigned long long b) {
    asm("fma.rn.f32x2 %0, %1, %2, %0;" : "+l"(acc) : "l"(a), "l"(b));
}
__device__ __forceinline__ unsigned long long add2(unsigned long long a,
                                                   unsigned long long b) {
    unsigned long long r;
    asm("add.rn.f32x2 %0, %1, %2;" : "=l"(r) : "l"(a), "l"(b));
    return r;
}

// Issue this warp's 16 X rows (2 commit groups of 8 rows), swizzled store.
__device__ __forceinline__ void issue_rows(const float* __restrict__ X, int b,
                                           uint32_t xs_base, int row0, int lane) {
    const float* Xg = X + (size_t)b * (LSEQ * DIM);
    #pragma unroll
    for (int g2 = 0; g2 < 2; g2++) {
        #pragma unroll
        for (int h = 0; h < 4; h++) {
            int s   = lane + 32 * h;               // 0..127
            int r8  = s >> 4;
            int col = s & 15;                      // 16B data chunk
            int row = row0 + 8 * g2 + r8;
            int sw  = col ^ (row & 15);            // swizzled chunk
            cp_async16(xs_base + (uint32_t)(row * 256 + sw * 16),
                       (const void*)(Xg + row * DIM + col * 4));
        }
        cp_commit();
    }
}

// Masked softmax for batch b into wt (warps 0..7 only; k = warp id).
__device__ __forceinline__ void do_softmax(float* __restrict__ wt,
                                           const int* __restrict__ seqlen,
                                           int b, int k, int lane) {
    const int slen = seqlen[b];
    float v[16];
    #pragma unroll
    for (int j = 0; j < 16; j++) {
        int l = lane + 32 * j;
        float bv = g_B[k * LSEQ + l];
        v[j] = (l < slen) ? bv : NEGV;
    }
    float m = v[0];
    #pragma unroll
    for (int j = 1; j < 16; j++) m = fmaxf(m, v[j]);
    #pragma unroll
    for (int off = 16; off > 0; off >>= 1)
        m = fmaxf(m, __shfl_xor_sync(0xffffffffu, m, off));
    float s = 0.f;
    #pragma unroll
    for (int j = 0; j < 16; j++) { v[j] = __expf(v[j] - m); s += v[j]; }
    #pragma unroll
    for (int off = 16; off > 0; off >>= 1)
        s += __shfl_xor_sync(0xffffffffu, s, off);
    float inv = 1.0f / s;
    #pragma unroll
    for (int j = 0; j < 16; j++)
        wt[(lane + 32 * j) * 8 + k] = v[j] * inv;   // W^T[l][k]
}

// Persistent kernel: one routing iteration. Warp-specialized step 4:
// warps 0-7 softmax(n+1), warps 8-23 epilogue, warps 24-31 idle.
// Accumulator ownership: acc2[dd*4+kp] holds d = lane + 32*dd (2-way CPART banks).
template<int LAST>
__global__ void __launch_bounds__(NTHREADS, 1)
route_kernel(const float* __restrict__ X, const float* __restrict__ Sg,
             const int* __restrict__ seqlen, float* __restrict__ out)
{
    extern __shared__ float sm[];
    const int tid  = threadIdx.x;
    const int w    = tid >> 5;            // 32 warps
    const int lane = tid & 31;
    const uint32_t xs_base = (uint32_t)__cvta_generic_to_shared(&sm[XS_OFF]);
    const int row0 = w * 16;              // this warp's X rows [row0, row0+16)

    int b = blockIdx.x;

    // prologue
    issue_rows(X, b, xs_base, row0, lane);
    {
        int j = tid;                      // 1024 float4s = S [64][64]
        int d = j >> 4, o4 = (j & 15) * 4;
        float4 v = *(const float4*)(Sg + j * 4);
        float* p = &sm[SS_OFF + d * 67 + o4];
        p[0] = v.x; p[1] = v.y; p[2] = v.z; p[3] = v.w;
    }
    if (w < 8) do_softmax(&sm[WT0_OFF], seqlen, b, w, lane);
    __syncthreads();

    int par = 0;
    for (; b < BATCH; b += GRID, par ^= 1) {
        const int bn = b + GRID;
        const float* wt  = &sm[par ? WT1_OFF : WT0_OFF];
        float*       wtn = &sm[par ? WT0_OFF : WT1_OFF];

        // ---- pass 1: C'[k][d] = sum_l W[k][l]*X[l][d]; warp-private rows ----
        // d = lane (acc2[0..3]) and d = lane+32 (acc2[4..7]); both scalar LDS.32
        // are conflict-free under the chunk swizzle.
        unsigned long long acc2[8];
        #pragma unroll
        for (int i = 0; i < 8; i++) acc2[i] = 0ull;

        #pragma unroll
        for (int g2 = 0; g2 < 2; g2++) {
            if (g2 == 0) cp_wait<1>(); else cp_wait<0>();
            __syncwarp();
            #pragma unroll
            for (int r = 0; r < 8; r++) {
                int row = row0 + 8 * g2 + r;
                int rsw = row & 15;
                float xv0 = sm[XS_OFF + row * 64 +
                               ((((lane >> 2)    ) ^ rsw) << 2) + (lane & 3)];
                float xv1 = sm[XS_OFF + row * 64 +
                               ((((lane >> 2) + 8) ^ rsw) << 2) + (lane & 3)];
                ulonglong2 wA = *(const ulonglong2*)&wt[row * 8];
                ulonglong2 wB = *(const ulonglong2*)&wt[row * 8 + 4];
                unsigned long long xx0 = pack2(xv0);
                unsigned long long xx1 = pack2(xv1);
                fma2(acc2[0], xx0, wA.x); fma2(acc2[1], xx0, wA.y);
                fma2(acc2[2], xx0, wB.x); fma2(acc2[3], xx0, wB.y);
                fma2(acc2[4], xx1, wA.x); fma2(acc2[5], xx1, wA.y);
                fma2(acc2[6], xx1, wB.x); fma2(acc2[7], xx1, wB.y);
            }
        }

        // LAST: X dead after pass1 -> prefetch own rows now
        if (LAST && bn < BATCH) issue_rows(X, bn, xs_base, row0, lane);

        // ---- two-wave cross-warp reduction into CPART [16][64][10] ----
        // d = lane + 32*dd -> lane stride 10 floats -> 2-way worst case.
        if (w < 16) {
            #pragma unroll
            for (int dd = 0; dd < 2; dd++)
                #pragma unroll
                for (int kp = 0; kp < 4; kp++) {
                    int d = lane + 32 * dd;
                    *(unsigned long long*)&sm[CPART_OFF + w * 640 + d * CPS + 2 * kp]
                        = acc2[dd * 4 + kp];
                }
        }
        __syncthreads();
        if (w >= 16) {
            int p = w - 16;
            #pragma unroll
            for (int dd = 0; dd < 2; dd++)
                #pragma unroll
                for (int kp = 0; kp < 4; kp++) {
                    int d = lane + 32 * dd;
                    unsigned long long* ptr =
                        (unsigned long long*)&sm[CPART_OFF + p * 640 + d * CPS + 2 * kp];
                    *ptr = add2(*ptr, acc2[dd * 4 + kp]);
                }
        }
        __syncthreads();
        if (tid < 512) {
            int k = tid >> 6, d = tid & 63;
            float s = 0.f;
            #pragma unroll
            for (int p = 0; p < 16; p++) s += sm[CPART_OFF + p * 640 + d * CPS + k];
            sm[CP_OFF + k * 64 + d] = s;
        }
        __syncthreads();

        // ---- step 4: softmax(n+1) on warps 0-7 || epilogue on warps 8-23 ----
        if (w < 8) {
            if (bn < BATCH) do_softmax(wtn, seqlen, bn, w, lane);
        } else if (w < 24) {
            const int t = tid - 256;          // 0..511
            const int k = t >> 6, o = t & 63; // warp spans one k

            // Cs[k][o] = sum_d C'[k][d]*S[d][o]
            float a = 0.f;
            #pragma unroll
            for (int d = 0; d < 64; d++)
                a += sm[CP_OFF + k * 64 + d] * sm[SS_OFF + d * 67 + o];
            sm[CS_OFF + k * 65 + o] = a;
            bar_epi();

            if (t < 64) {                     // squash scale (2 warps)
                float sq = 0.f;
                #pragma unroll
                for (int k8 = 0; k8 < 8; k8++) {
                    float cv = sm[CS_OFF + k8 * 65 + t];
                    sq += cv * cv;
                }
                sm[SCALE_OFF + t] = (sq / (1.0f + sq)) * rsqrtf(sq + 1e-9f);
            }
            bar_epi();

            float hv = sm[SCALE_OFF + o] * sm[CS_OFF + k * 65 + o];
            if (LAST) {
                out[(size_t)b * 512 + t] = hv;            // t == k*64+o
            } else {
                sm[CS_OFF + k * 65 + o] = hv;             // high, in place
                bar_epi();
                // hs[k][i] = sum_o high[k][o]*S[i][o]  -> hs^T[i][k]
                const int i = o;
                float h = 0.f;
                #pragma unroll
                for (int oo = 0; oo < 64; oo++)
                    h += sm[CS_OFF + k * 65 + oo] * sm[SS_OFF + i * 67 + oo];
                sm[HST_OFF + i * 8 + k] = h;
            }
        }
        __syncthreads();   // joins soft/epi/idle; publishes wtn + HST

        if (!LAST) {
            // ---- pass 2 (own rows): delta[k][l] = sum_i hs[k][i]*X[l][i] ----
            const int row = row0 + (lane >> 1);
            const int ks  = lane & 1;          // capsules [4ks, 4ks+4)
            const int rsw = row & 15;
            unsigned long long dacc2[2] = {0ull, 0ull};
            #pragma unroll
            for (int q = 0; q < 16; q++) {
                float4 x = *(const float4*)&sm[XS_OFF + row * 64 + ((q ^ rsw) << 2)];
                #pragma unroll
                for (int r = 0; r < 4; r++) {
                    float xvf = (r == 0) ? x.x : (r == 1) ? x.y : (r == 2) ? x.z : x.w;
                    unsigned long long xx = pack2(xvf);
                    ulonglong2 hA =
                        *(const ulonglong2*)&sm[HST_OFF + (q * 4 + r) * 8 + 4 * ks];
                    fma2(dacc2[0], xx, hA.x);
                    fma2(dacc2[1], xx, hA.y);
                }
            }
            // own rows dead -> prefetch next batch (no barrier to next pass1)
            if (bn < BATCH) issue_rows(X, bn, xs_base, row0, lane);

            float* sc = &g_scratch[(size_t)b * 4096 + row];
            unsigned int u0, u1, u2, u3;
            asm("mov.b64 {%0, %1}, %2;" : "=r"(u0), "=r"(u1) : "l"(dacc2[0]));
            asm("mov.b64 {%0, %1}, %2;" : "=r"(u2), "=r"(u3) : "l"(dacc2[1]));
            sc[(4 * ks + 0) * 512] = __uint_as_float(u0);
            sc[(4 * ks + 1) * 512] = __uint_as_float(u1);
            sc[(4 * ks + 2) * 512] = __uint_as_float(u2);
            sc[(4 * ks + 3) * 512] = __uint_as_float(u3);
        }
    }
}

// Deterministic 2-stage cross-batch reduction of deltas into g_B
__global__ void reduce1_kernel() {
    int j = blockIdx.x * 256 + threadIdx.x;      // 0..4095
    int base = blockIdx.y * 16;
    float s = 0.f;
    #pragma unroll
    for (int i = 0; i < 16; i++) s += g_scratch[(size_t)(base + i) * 4096 + j];
    g_part[(size_t)blockIdx.y * 4096 + j] = s;
}
__global__ void reduce2_kernel() {
    int j = blockIdx.x * 256 + threadIdx.x;
    float s = 0.f;
    #pragma unroll
    for (int i = 0; i < 64; i++) s += g_part[(size_t)i * 4096 + j];
    g_B[j] += s;
}

extern "C" void kernel_launch(void* const* d_in, const int* in_sizes, int n_in,
                              void* d_out, int out_size)
{
    const float* X     = (const float*)d_in[0];  // low_capsule [1024,512,64]
    const float* Binit = (const float*)d_in[1];  // B_init [1,8,512]
    const float* S     = (const float*)d_in[2];  // S [64,64]
    const int*   seq   = (const int*)d_in[3];    // seq_len [1024,1]
    float* out = (float*)d_out;

    cudaFuncSetAttribute(route_kernel<0>, cudaFuncAttributeMaxDynamicSharedMemorySize, SMEM_BYTES);
    cudaFuncSetAttribute(route_kernel<1>, cudaFuncAttributeMaxDynamicSharedMemorySize, SMEM_BYTES);

    void* bptr = nullptr;
    cudaGetSymbolAddress(&bptr, g_B);
    cudaMemcpyAsync(bptr, Binit, KCAP * LSEQ * sizeof(float),
                    cudaMemcpyDeviceToDevice, 0);

    // iter 0
    route_kernel<0><<<GRID, NTHREADS, SMEM_BYTES>>>(X, S, seq, out);
    reduce1_kernel<<<dim3(16, 64), 256>>>();
    reduce2_kernel<<<16, 256>>>();
    // iter 1
    route_kernel<0><<<GRID, NTHREADS, SMEM_BYTES>>>(X, S, seq, out);
    reduce1_kernel<<<dim3(16, 64), 256>>>();
    reduce2_kernel<<<16, 256>>>();
    // iter 2 (final): writes high
    route_kernel<1><<<GRID, NTHREADS, SMEM_BYTES>>>(X, S, seq, out);
}